// round 2
// baseline (speedup 1.0000x reference)
#include <cuda_runtime.h>
#include <math.h>

#define BB 64
#define SS 128
#define HH 1024
#define GG 4096
#define VV 50257
#define TT 32

typedef unsigned long long ull;

// ---------------- scratch (device globals; no allocations) ----------------
__device__ float g_h[2 * BB * HH];
__device__ float g_c[2 * BB * HH];
__device__ float g_x[BB * HH];                 // decode-step input embedding
__device__ float g_part[8ull * BB * GG];       // K-split partial gate sums
__device__ float g_Xg[(size_t)SS * BB * GG];   // precomputed x@W_ih^T + b_ih + b_hh
__device__ int   g_len[BB];
__device__ float g_pv[BB * 32];
__device__ int   g_pi[BB * 32];

// ---------------- f32x2 helpers (FFMA2: 2 MACs/instr on sm_103a) ----------
__device__ __forceinline__ ull ffma2(ull a, ull b, ull c) {
    ull d;
    asm("fma.rn.f32x2 %0, %1, %2, %3;" : "=l"(d) : "l"(a), "l"(b), "l"(c));
    return d;
}
__device__ __forceinline__ ull splat2(float x) {
    ull r; unsigned xi = __float_as_uint(x);
    asm("mov.b64 %0, {%1, %1};" : "=l"(r) : "r"(xi));
    return r;
}
__device__ __forceinline__ float2 unpack2(ull v) {
    unsigned lo, hi;
    asm("mov.b64 {%0, %1}, %2;" : "=r"(lo), "=r"(hi) : "l"(v));
    return make_float2(__uint_as_float(lo), __uint_as_float(hi));
}
__device__ __forceinline__ float sigmoidf_(float x) { return 1.0f / (1.0f + expf(-x)); }

// ---------------- tiny prep kernels ----------------
__global__ void k_len(const int* __restrict__ ids) {
    __shared__ int cnt[4];
    int b = blockIdx.x;
    int nz = (ids[b * SS + threadIdx.x] != 0) ? 1 : 0;
    unsigned m = __ballot_sync(0xffffffffu, nz);
    if ((threadIdx.x & 31) == 0) cnt[threadIdx.x >> 5] = __popc(m);
    __syncthreads();
    if (threadIdx.x == 0) g_len[b] = cnt[0] + cnt[1] + cnt[2] + cnt[3];
}

__global__ void k_zero() {
    int i = blockIdx.x * 256 + threadIdx.x;   // covers BB*HH (buffer 0)
    g_h[i] = 0.0f;
    g_c[i] = 0.0f;
}

// ---------------- Xg = emb[ids] @ W_ih^T + b_ih + b_hh  (M=8192,N=4096,K=1024)
// 128x128 tile, BK=16, 256 threads, 8x8 microtile packed as f32x2 along N.
__global__ __launch_bounds__(256) void k_embed_gemm(
    const int* __restrict__ ids, const float* __restrict__ emb,
    const float* __restrict__ W_ih, const float* __restrict__ b_ih,
    const float* __restrict__ b_hh)
{
    __shared__ float As[16][128];  // [k][m]
    __shared__ float Bs[16][128];  // [k][n]
    __shared__ int toks[128];
    const int tid = threadIdx.x;
    const int m0 = blockIdx.y * 128;
    const int n0 = blockIdx.x * 128;
    if (tid < 128) {
        int m = m0 + tid;
        int b = m & (BB - 1);
        int s = m >> 6;
        toks[tid] = ids[b * SS + s];
    }
    __syncthreads();
    const int tx = tid & 15, ty = tid >> 4;
    const int mo = ty * 8, no = tx * 8;
    ull acc[8][4];
#pragma unroll
    for (int i = 0; i < 8; i++)
#pragma unroll
        for (int j = 0; j < 4; j++) acc[i][j] = 0ull;

    for (int k0 = 0; k0 < HH; k0 += 16) {
#pragma unroll
        for (int q0 = 0; q0 < 512; q0 += 256) {
            int q = q0 + tid;
            int r = q >> 2, kk = (q & 3) << 2;
            float4 v = *(const float4*)(emb + (size_t)toks[r] * HH + k0 + kk);
            As[kk][r] = v.x; As[kk + 1][r] = v.y; As[kk + 2][r] = v.z; As[kk + 3][r] = v.w;
            float4 w = *(const float4*)(W_ih + (size_t)(n0 + r) * HH + k0 + kk);
            Bs[kk][r] = w.x; Bs[kk + 1][r] = w.y; Bs[kk + 2][r] = w.z; Bs[kk + 3][r] = w.w;
        }
        __syncthreads();
#pragma unroll
        for (int k = 0; k < 16; k++) {
            const ull* bp = (const ull*)&Bs[k][no];
            ull b2_0 = bp[0], b2_1 = bp[1], b2_2 = bp[2], b2_3 = bp[3];
            float4 a0 = *(const float4*)&As[k][mo];
            float4 a1 = *(const float4*)&As[k][mo + 4];
            float av[8] = {a0.x, a0.y, a0.z, a0.w, a1.x, a1.y, a1.z, a1.w};
#pragma unroll
            for (int i = 0; i < 8; i++) {
                ull a2 = splat2(av[i]);
                acc[i][0] = ffma2(a2, b2_0, acc[i][0]);
                acc[i][1] = ffma2(a2, b2_1, acc[i][1]);
                acc[i][2] = ffma2(a2, b2_2, acc[i][2]);
                acc[i][3] = ffma2(a2, b2_3, acc[i][3]);
            }
        }
        __syncthreads();
    }
#pragma unroll
    for (int i = 0; i < 8; i++) {
        int m = m0 + mo + i;
        float* dst = g_Xg + (size_t)m * GG + n0 + no;
#pragma unroll
        for (int j = 0; j < 4; j++) {
            float2 cc = unpack2(acc[i][j]);
            int n = n0 + no + 2 * j;
            cc.x += b_ih[n] + b_hh[n];
            cc.y += b_ih[n + 1] + b_hh[n + 1];
            *(float2*)(dst + 2 * j) = cc;
        }
    }
}

// ---------------- partial gate GEMM: part[pb+cy] = A(64xH slice K=256) @ W^T tile
// grid (GG/64, 4); block 256; 64(b) x 64(j) tile, thread 4x4, f32x2 along j.
__global__ __launch_bounds__(256) void k_gates_part(
    int aSel /*0,1: h buffer; 2: g_x*/, const float* __restrict__ Wt, int partBase)
{
    __shared__ float As[32][64];  // [k][b]
    __shared__ float Ws[32][64];  // [k][j]
    const float* A = (aSel == 2) ? g_x : (g_h + aSel * (BB * HH));
    const int tid = threadIdx.x;
    const int j0 = blockIdx.x * 64;
    const int k0 = blockIdx.y * 256;
    float* out = g_part + (size_t)(partBase + blockIdx.y) * (BB * GG);
    const int tx = tid & 15, ty = tid >> 4;
    const int bo = ty * 4, jo = tx * 4;
    ull acc[4][2];
#pragma unroll
    for (int i = 0; i < 4; i++) { acc[i][0] = 0ull; acc[i][1] = 0ull; }

    for (int kk = 0; kk < 256; kk += 32) {
#pragma unroll
        for (int q0 = 0; q0 < 512; q0 += 256) {
            int q = q0 + tid;
            int r = q >> 3, kq = (q & 7) << 2;
            float4 v = *(const float4*)(A + (size_t)r * HH + k0 + kk + kq);
            As[kq][r] = v.x; As[kq + 1][r] = v.y; As[kq + 2][r] = v.z; As[kq + 3][r] = v.w;
            float4 w = *(const float4*)(Wt + (size_t)(j0 + r) * HH + k0 + kk + kq);
            Ws[kq][r] = w.x; Ws[kq + 1][r] = w.y; Ws[kq + 2][r] = w.z; Ws[kq + 3][r] = w.w;
        }
        __syncthreads();
#pragma unroll
        for (int k = 0; k < 32; k++) {
            const ull* wp = (const ull*)&Ws[k][jo];
            ull b2_0 = wp[0], b2_1 = wp[1];
            float4 a4 = *(const float4*)&As[k][bo];
            float av[4] = {a4.x, a4.y, a4.z, a4.w};
#pragma unroll
            for (int i = 0; i < 4; i++) {
                ull a2 = splat2(av[i]);
                acc[i][0] = ffma2(a2, b2_0, acc[i][0]);
                acc[i][1] = ffma2(a2, b2_1, acc[i][1]);
            }
        }
        __syncthreads();
    }
#pragma unroll
    for (int i = 0; i < 4; i++) {
        int b = bo + i;
#pragma unroll
        for (int j = 0; j < 2; j++) {
            float2 cc = unpack2(acc[i][j]);
            *(float2*)(out + (size_t)b * GG + j0 + jo + 2 * j) = cc;
        }
    }
}

// ---------------- gate combine + activations + state update ----------------
// s >= 0: prompt step (adds Xg[s], masked by length). s < 0: decode (adds biases).
__global__ void k_update(int s, int cur, int nparts,
                         const float* __restrict__ bi, const float* __restrict__ bh)
{
    int idx = blockIdx.x * blockDim.x + threadIdx.x;   // < BB*HH
    int b = idx >> 10;
    int hc = idx & 1023;
    const float* xadd = (s >= 0) ? (g_Xg + (size_t)s * BB * GG) : nullptr;
    const float* hin = g_h + cur * (BB * HH);
    const float* cin = g_c + cur * (BB * HH);
    float* hout = g_h + (cur ^ 1) * (BB * HH);
    float* cout = g_c + (cur ^ 1) * (BB * HH);

    float g4[4];
#pragma unroll
    for (int gi = 0; gi < 4; gi++) {
        int j = gi * HH + hc;
        float v = xadd ? xadd[(size_t)b * GG + j] : (bi[j] + bh[j]);
        for (int p = 0; p < nparts; p++)
            v += g_part[(size_t)p * BB * GG + (size_t)b * GG + j];
        g4[gi] = v;
    }
    float ig = sigmoidf_(g4[0]);
    float fg = sigmoidf_(g4[1]);
    float gg = tanhf(g4[2]);
    float og = sigmoidf_(g4[3]);
    float cn = fg * cin[idx] + ig * gg;
    float hn = og * tanhf(cn);
    bool valid = (s < 0) || (s < g_len[b]);
    hout[idx] = valid ? hn : hin[idx];
    cout[idx] = valid ? cn : cin[idx];
}

// ---------------- logits: out[b,t,:] = h @ W_fc^T + b_fc ----------------
// grid ceil(V/64); 64(b) x 64(v) tile, K=1024, thread 4x4, f32x2 along v.
__global__ __launch_bounds__(256) void k_logits(
    int cur, const float* __restrict__ W_fc, const float* __restrict__ b_fc,
    float* __restrict__ outbuf, int t)
{
    __shared__ float Hs[32][64];
    __shared__ float Ws[32][64];
    const float* h = g_h + cur * (BB * HH);
    const int tid = threadIdx.x;
    const int v0 = blockIdx.x * 64;
    const int tx = tid & 15, ty = tid >> 4;
    const int bo = ty * 4, vo = tx * 4;
    ull acc[4][2];
#pragma unroll
    for (int i = 0; i < 4; i++) { acc[i][0] = 0ull; acc[i][1] = 0ull; }

    for (int k0 = 0; k0 < HH; k0 += 32) {
#pragma unroll
        for (int q0 = 0; q0 < 512; q0 += 256) {
            int q = q0 + tid;
            int r = q >> 3, kq = (q & 7) << 2;
            float4 v = *(const float4*)(h + (size_t)r * HH + k0 + kq);
            Hs[kq][r] = v.x; Hs[kq + 1][r] = v.y; Hs[kq + 2][r] = v.z; Hs[kq + 3][r] = v.w;
            float4 w = make_float4(0.f, 0.f, 0.f, 0.f);
            if (v0 + r < VV) w = *(const float4*)(W_fc + (size_t)(v0 + r) * HH + k0 + kq);
            Ws[kq][r] = w.x; Ws[kq + 1][r] = w.y; Ws[kq + 2][r] = w.z; Ws[kq + 3][r] = w.w;
        }
        __syncthreads();
#pragma unroll
        for (int k = 0; k < 32; k++) {
            const ull* wp = (const ull*)&Ws[k][vo];
            ull b2_0 = wp[0], b2_1 = wp[1];
            float4 a4 = *(const float4*)&Hs[k][bo];
            float av[4] = {a4.x, a4.y, a4.z, a4.w};
#pragma unroll
            for (int i = 0; i < 4; i++) {
                ull a2 = splat2(av[i]);
                acc[i][0] = ffma2(a2, b2_0, acc[i][0]);
                acc[i][1] = ffma2(a2, b2_1, acc[i][1]);
            }
        }
        __syncthreads();
    }
#pragma unroll
    for (int i = 0; i < 4; i++) {
        int b = bo + i;
        float* dst = outbuf + ((size_t)b * TT + t) * VV;
#pragma unroll
        for (int j = 0; j < 2; j++) {
            float2 cc = unpack2(acc[i][j]);
            int v = v0 + vo + 2 * j;
            if (v < VV)     dst[v]     = cc.x + b_fc[v];
            if (v + 1 < VV) dst[v + 1] = cc.y + b_fc[v + 1];
        }
    }
}

// ---------------- argmax (first-max tie-break, matching jnp.argmax) --------
__global__ void k_argmax_part(const float* __restrict__ outbuf, int t) {
    __shared__ float sv[256];
    __shared__ int   si[256];
    int b = blockIdx.y;
    const float* row = outbuf + ((size_t)b * TT + t) * VV;
    int chunk = (VV + 31) / 32;
    int start = blockIdx.x * chunk;
    int end = min(start + chunk, VV);
    float best = -3.4e38f; int bi = VV;
    for (int v = start + threadIdx.x; v < end; v += 256) {
        float x = row[v];
        if (x > best || (x == best && v < bi)) { best = x; bi = v; }
    }
    sv[threadIdx.x] = best; si[threadIdx.x] = bi;
    __syncthreads();
    for (int st = 128; st > 0; st >>= 1) {
        if (threadIdx.x < st) {
            float o = sv[threadIdx.x + st]; int oi = si[threadIdx.x + st];
            if (o > sv[threadIdx.x] || (o == sv[threadIdx.x] && oi < si[threadIdx.x])) {
                sv[threadIdx.x] = o; si[threadIdx.x] = oi;
            }
        }
        __syncthreads();
    }
    if (threadIdx.x == 0) { g_pv[b * 32 + blockIdx.x] = sv[0]; g_pi[b * 32 + blockIdx.x] = si[0]; }
}

__global__ void k_argmax_fin(const float* __restrict__ emb) {
    __shared__ float sv[32];
    __shared__ int   si[32];
    __shared__ int   stok;
    int b = blockIdx.x;
    if (threadIdx.x < 32) { sv[threadIdx.x] = g_pv[b * 32 + threadIdx.x]; si[threadIdx.x] = g_pi[b * 32 + threadIdx.x]; }
    __syncthreads();
    if (threadIdx.x == 0) {
        float best = sv[0]; int bi = si[0];
        for (int q = 1; q < 32; q++)
            if (sv[q] > best || (sv[q] == best && si[q] < bi)) { best = sv[q]; bi = si[q]; }
        stok = bi;
    }
    __syncthreads();
    int tok = stok;
    float4 v = *(const float4*)(emb + (size_t)tok * HH + threadIdx.x * 4);
    *(float4*)(g_x + (size_t)b * HH + threadIdx.x * 4) = v;
}

// ---------------- driver ----------------
extern "C" void kernel_launch(void* const* d_in, const int* in_sizes, int n_in,
                              void* d_out, int out_size)
{
    const int*   ids  = (const int*)d_in[0];
    // d_in[1] = max_new_tokens (fixed 32, baked into the static graph)
    const float* emb  = (const float*)d_in[2];
    const float* W_ih = (const float*)d_in[3];
    const float* W_hh = (const float*)d_in[4];
    const float* b_ih = (const float*)d_in[5];
    const float* b_hh = (const float*)d_in[6];
    const float* W_fc = (const float*)d_in[7];
    const float* b_fc = (const float*)d_in[8];
    float* out = (float*)d_out;

    k_len<<<BB, 128>>>(ids);
    k_zero<<<(BB * HH) / 256, 256>>>();

    dim3 egrid(GG / 128, (BB * SS) / 128);
    k_embed_gemm<<<egrid, 256>>>(ids, emb, W_ih, b_ih, b_hh);

    int cur = 0;
    for (int s = 0; s < SS; s++) {
        k_gates_part<<<dim3(GG / 64, 4), 256>>>(cur, W_hh, 0);
        k_update<<<(BB * HH) / 256, 256>>>(s, cur, 4, b_ih, b_hh);
        cur ^= 1;
    }

    const int lgrid = (VV + 63) / 64;
    k_logits<<<lgrid, 256>>>(cur, W_fc, b_fc, out, 0);

    for (int t = 1; t < TT; t++) {
        k_argmax_part<<<dim3(32, BB), 256>>>(out, t - 1);
        k_argmax_fin<<<BB, 256>>>(emb);
        k_gates_part<<<dim3(GG / 64, 4), 256>>>(2, W_ih, 0);    // x @ W_ih^T  -> parts 0..3
        k_gates_part<<<dim3(GG / 64, 4), 256>>>(cur, W_hh, 4);  // h @ W_hh^T  -> parts 4..7
        k_update<<<(BB * HH) / 256, 256>>>(-1, cur, 8, b_ih, b_hh);
        cur ^= 1;
        k_logits<<<lgrid, 256>>>(cur, W_fc, b_fc, out, t);
    }
}